// round 2
// baseline (speedup 1.0000x reference)
#include <cuda_runtime.h>

#define MPTS 16384
#define NPTS 16384
#define TILE 2048
#define NTHREADS 256
#define WARPS (NTHREADS / 32)
#define QPW 2  // queries per warp
#define FINF 3.402823466e38f

// Scratch: refs repacked as (x, y, z, |r|^2). 256 KB device global (allowed).
__device__ float4 g_ref4[MPTS];

__global__ void prep_kernel(const float* __restrict__ ref) {
    int i = blockIdx.x * blockDim.x + threadIdx.x;
    if (i < MPTS) {
        float x = ref[3 * i + 0];
        float y = ref[3 * i + 1];
        float z = ref[3 * i + 2];
        g_ref4[i] = make_float4(x, y, z, fmaf(x, x, fmaf(y, y, z * z)));
    }
}

// Warp-collective finalize for one query: merge per-lane top-3 into warp
// top-3, then lane 0 computes IDW-interpolated flow.
__device__ __forceinline__ void finalize(
    float b0, float b1, float b2, int i0, int i1, int i2,
    int lane, float qx, float qy, float qz,
    const float* __restrict__ flow, float* __restrict__ out, int q)
{
    float best[3];
    int bidx[3];
    #pragma unroll
    for (int r = 0; r < 3; r++) {
        float v = b0;
        int vi = i0;
        #pragma unroll
        for (int off = 16; off; off >>= 1) {
            float ov = __shfl_xor_sync(0xffffffffu, v, off);
            int oi = __shfl_xor_sync(0xffffffffu, vi, off);
            if (ov < v || (ov == v && oi < vi)) { v = ov; vi = oi; }
        }
        best[r] = v;
        bidx[r] = vi;
        // The lane owning the winner pops it (indices are unique).
        if (v == b0 && vi == i0) {
            b0 = b1; i0 = i1;
            b1 = b2; i1 = i2;
            b2 = FINF; i2 = 0x7fffffff;
        }
    }
    if (lane == 0) {
        float hq = fmaf(qx, qx, fmaf(qy, qy, qz * qz));
        float wsum = 0.f, fx = 0.f, fy = 0.f, fz = 0.f;
        #pragma unroll
        for (int r = 0; r < 3; r++) {
            float d2 = best[r] + hq;  // add back |q|^2
            float dd = sqrtf(fmaxf(d2, 1e-12f));
            float w = 1.0f / (dd + 1e-8f);
            int ii = bidx[r];
            wsum += w;
            fx = fmaf(w, flow[3 * ii + 0], fx);
            fy = fmaf(w, flow[3 * ii + 1], fy);
            fz = fmaf(w, flow[3 * ii + 2], fz);
        }
        float inv = 1.0f / wsum;
        out[3 * q + 0] = fx * inv;
        out[3 * q + 1] = fy * inv;
        out[3 * q + 2] = fz * inv;
    }
}

__global__ void __launch_bounds__(NTHREADS, 1) knn_kernel(
    const float* __restrict__ query,
    const float* __restrict__ flow,
    float* __restrict__ out)
{
    __shared__ float4 tile[TILE];
    const int warp = threadIdx.x >> 5;
    const int lane = threadIdx.x & 31;
    const int qbase = (blockIdx.x * WARPS + warp) * QPW;

    // Two queries per warp (broadcast loads: all lanes same address).
    float qx0 = query[3 * qbase + 0];
    float qy0 = query[3 * qbase + 1];
    float qz0 = query[3 * qbase + 2];
    float qx1 = query[3 * qbase + 3];
    float qy1 = query[3 * qbase + 4];
    float qz1 = query[3 * qbase + 5];

    // Per-lane top-3 (sorted ascending) of score = |r|^2 - 2 q.r
    float a0 = FINF, a1 = FINF, a2 = FINF;
    int ai0 = 0, ai1 = 0, ai2 = 0;
    float c0 = FINF, c1 = FINF, c2 = FINF;
    int ci0 = 0, ci1 = 0, ci2 = 0;

    for (int t = 0; t < MPTS; t += TILE) {
        __syncthreads();
        #pragma unroll
        for (int e = 0; e < TILE / NTHREADS; e++)
            tile[threadIdx.x + e * NTHREADS] = g_ref4[t + threadIdx.x + e * NTHREADS];
        __syncthreads();

        #pragma unroll 4
        for (int j = lane; j < TILE; j += 32) {
            float4 r = tile[j];
            float s0 = qx0 * r.x;
            s0 = fmaf(qy0, r.y, s0);
            s0 = fmaf(qz0, r.z, s0);
            float d0 = fmaf(-2.0f, s0, r.w);
            float s1 = qx1 * r.x;
            s1 = fmaf(qy1, r.y, s1);
            s1 = fmaf(qz1, r.z, s1);
            float d1 = fmaf(-2.0f, s1, r.w);
            if (d0 < a2) {
                int idx = t + j;
                if (d0 < a0)      { a2 = a1; ai2 = ai1; a1 = a0; ai1 = ai0; a0 = d0; ai0 = idx; }
                else if (d0 < a1) { a2 = a1; ai2 = ai1; a1 = d0; ai1 = idx; }
                else              { a2 = d0; ai2 = idx; }
            }
            if (d1 < c2) {
                int idx = t + j;
                if (d1 < c0)      { c2 = c1; ci2 = ci1; c1 = c0; ci1 = ci0; c0 = d1; ci0 = idx; }
                else if (d1 < c1) { c2 = c1; ci2 = ci1; c1 = d1; ci1 = idx; }
                else              { c2 = d1; ci2 = idx; }
            }
        }
    }

    finalize(a0, a1, a2, ai0, ai1, ai2, lane, qx0, qy0, qz0, flow, out, qbase + 0);
    finalize(c0, c1, c2, ci0, ci1, ci2, lane, qx1, qy1, qz1, flow, out, qbase + 1);
}

extern "C" void kernel_launch(void* const* d_in, const int* in_sizes, int n_in,
                              void* d_out, int out_size) {
    const float* query = (const float*)d_in[0];
    const float* ref   = (const float*)d_in[1];
    const float* flow  = (const float*)d_in[2];
    // d_in[3] is k (always 3 here; compile-time K=3).
    float* out = (float*)d_out;

    prep_kernel<<<MPTS / NTHREADS, NTHREADS>>>(ref);
    knn_kernel<<<NPTS / (WARPS * QPW), NTHREADS>>>(query, flow, out);
}